// round 1
// baseline (speedup 1.0000x reference)
#include <cuda_runtime.h>

// ---------------------------------------------------------------------------
// ActivityDecaySNN: 3-layer LIF SNN forward.
//   T=50, B=512, D_IN=784, HID=800, OUT=10
//   Structure: GEMM1 -> LIF1 -> GEMM2 -> LIF2 -> GEMM3(N=10) -> LIF3+sum
// Outputs concatenated in d_out: out[512*10] | s1r[50*512*800] |
//                                s2r[50*512*800] | s3r[50*512*10]
// ---------------------------------------------------------------------------

#define T_STEPS 50
#define BATCH   512
#define DIN     784
#define HID     800
#define NOUT    10
#define M_ROWS  (T_STEPS * BATCH)   // 25600

// Scratch: static device globals (no runtime allocation allowed).
__device__ float g_c1[(size_t)M_ROWS * HID];   // 81.9 MB
__device__ float g_c2[(size_t)M_ROWS * HID];   // 81.9 MB
__device__ float g_c3[(size_t)M_ROWS * NOUT];  // 1.0 MB

// ---------------------------------------------------------------------------
// SGEMM (NT): C[M,N] = A[M,K] @ W[N,K]^T + bias[N]
// BM=BN=128, BK=16, 256 threads, 8x8 register tile, double-buffered smem.
// Assumes M % 128 == 0 and K % 16 == 0 (true for all our shapes).
// N handled with predication (N=800 -> last tile partial).
// ---------------------------------------------------------------------------
__global__ __launch_bounds__(256, 2)
void sgemm_nt_bias(const float* __restrict__ A, const float* __restrict__ W,
                   const float* __restrict__ bias, float* __restrict__ C,
                   int M, int N, int K)
{
    constexpr int BM = 128, BN = 128, BK = 16;
    __shared__ float As[2][BK][BM];
    __shared__ float Ws[2][BK][BN];

    const int tid = threadIdx.x;
    const int tx  = tid & 15;    // n-direction (8 cols each)
    const int ty  = tid >> 4;    // m-direction (8 rows each)
    const int m0  = blockIdx.y * BM;
    const int n0  = blockIdx.x * BN;

    // global->smem load mapping: 2048 floats per tile per operand,
    // 256 threads * 2 float4 each. ldRow in [0,64), ldCol in {0,4,8,12}.
    const int ldRow = tid >> 2;
    const int ldCol = (tid & 3) << 2;

    float acc[8][8];
    #pragma unroll
    for (int i = 0; i < 8; ++i)
        #pragma unroll
        for (int j = 0; j < 8; ++j) acc[i][j] = 0.0f;

    const int numTiles = K / BK;
    float4 aReg[2], wReg[2];

    // ---- prologue: load tile 0 ----
    #pragma unroll
    for (int r = 0; r < 2; ++r) {
        const int am = m0 + ldRow + r * 64;
        aReg[r] = *reinterpret_cast<const float4*>(A + (size_t)am * K + ldCol);
        const int wn = n0 + ldRow + r * 64;
        wReg[r] = (wn < N)
                ? *reinterpret_cast<const float4*>(W + (size_t)wn * K + ldCol)
                : make_float4(0.f, 0.f, 0.f, 0.f);
    }
    #pragma unroll
    for (int r = 0; r < 2; ++r) {
        const int mm = ldRow + r * 64;
        As[0][ldCol + 0][mm] = aReg[r].x;
        As[0][ldCol + 1][mm] = aReg[r].y;
        As[0][ldCol + 2][mm] = aReg[r].z;
        As[0][ldCol + 3][mm] = aReg[r].w;
        Ws[0][ldCol + 0][mm] = wReg[r].x;
        Ws[0][ldCol + 1][mm] = wReg[r].y;
        Ws[0][ldCol + 2][mm] = wReg[r].z;
        Ws[0][ldCol + 3][mm] = wReg[r].w;
    }
    __syncthreads();

    for (int t = 0; t < numTiles; ++t) {
        const int  buf     = t & 1;
        const bool hasNext = (t + 1 < numTiles);

        if (hasNext) {
            const int k0 = (t + 1) * BK;
            #pragma unroll
            for (int r = 0; r < 2; ++r) {
                const int am = m0 + ldRow + r * 64;
                aReg[r] = *reinterpret_cast<const float4*>(A + (size_t)am * K + k0 + ldCol);
                const int wn = n0 + ldRow + r * 64;
                wReg[r] = (wn < N)
                        ? *reinterpret_cast<const float4*>(W + (size_t)wn * K + k0 + ldCol)
                        : make_float4(0.f, 0.f, 0.f, 0.f);
            }
        }

        #pragma unroll
        for (int kk = 0; kk < BK; ++kk) {
            float af[8], wf[8];
            *reinterpret_cast<float4*>(&af[0]) =
                *reinterpret_cast<const float4*>(&As[buf][kk][ty * 8]);
            *reinterpret_cast<float4*>(&af[4]) =
                *reinterpret_cast<const float4*>(&As[buf][kk][ty * 8 + 4]);
            *reinterpret_cast<float4*>(&wf[0]) =
                *reinterpret_cast<const float4*>(&Ws[buf][kk][tx * 8]);
            *reinterpret_cast<float4*>(&wf[4]) =
                *reinterpret_cast<const float4*>(&Ws[buf][kk][tx * 8 + 4]);
            #pragma unroll
            for (int i = 0; i < 8; ++i)
                #pragma unroll
                for (int j = 0; j < 8; ++j)
                    acc[i][j] += af[i] * wf[j];
        }

        if (hasNext) {
            const int nb = buf ^ 1;
            #pragma unroll
            for (int r = 0; r < 2; ++r) {
                const int mm = ldRow + r * 64;
                As[nb][ldCol + 0][mm] = aReg[r].x;
                As[nb][ldCol + 1][mm] = aReg[r].y;
                As[nb][ldCol + 2][mm] = aReg[r].z;
                As[nb][ldCol + 3][mm] = aReg[r].w;
                Ws[nb][ldCol + 0][mm] = wReg[r].x;
                Ws[nb][ldCol + 1][mm] = wReg[r].y;
                Ws[nb][ldCol + 2][mm] = wReg[r].z;
                Ws[nb][ldCol + 3][mm] = wReg[r].w;
            }
            __syncthreads();
        }
    }

    // ---- epilogue: bias + store (predicated on N) ----
    #pragma unroll
    for (int i = 0; i < 8; ++i) {
        const int m = m0 + ty * 8 + i;
        #pragma unroll
        for (int j = 0; j < 8; ++j) {
            const int n = n0 + tx * 8 + j;
            if (n < N) C[(size_t)m * N + n] = acc[i][j] + bias[n];
        }
    }
}

// ---------------------------------------------------------------------------
// LIF recurrence over T for one layer: one thread per (b, h) lane.
//   reset_t = spk_{t-1} (subtract-reset from previous membrane, detached)
//   mem_t   = beta * mem_{t-1} + cur_t - reset_t * THRESH   (THRESH = 1)
//   spk_t   = (mem_t - 1 > 0)
// cur layout [T, BH], spk layout [T, BH] -> coalesced per timestep.
// ---------------------------------------------------------------------------
__global__ void lif_kernel(const float* __restrict__ cur,
                           float* __restrict__ spk,
                           const float* __restrict__ beta_ptr, int BH)
{
    const int idx = blockIdx.x * blockDim.x + threadIdx.x;
    if (idx >= BH) return;
    const float beta = fminf(fmaxf(beta_ptr[0], 0.0f), 1.0f);
    float mem = 0.0f, rst = 0.0f;
    #pragma unroll
    for (int t = 0; t < T_STEPS; ++t) {
        const float c = cur[(size_t)t * BH + idx];
        mem = beta * mem + c - rst;
        const float s = (mem - 1.0f > 0.0f) ? 1.0f : 0.0f;
        spk[(size_t)t * BH + idx] = s;
        rst = s;
    }
}

// ---------------------------------------------------------------------------
// Layer-3 GEMM: C3[M,10] = S2[M,800] @ W3[10,800]^T + b3.
// 8 warps/block, one row per warp; W3 staged in smem (32 KB).
// ---------------------------------------------------------------------------
__global__ __launch_bounds__(256)
void gemm3_kernel(const float* __restrict__ S2, const float* __restrict__ W3,
                  const float* __restrict__ b3, float* __restrict__ C3, int M)
{
    __shared__ float w3s[NOUT * HID];  // 8000 floats = 32 KB
    for (int i = threadIdx.x; i < NOUT * HID; i += 256) w3s[i] = W3[i];
    __syncthreads();

    const int warp = threadIdx.x >> 5;
    const int lane = threadIdx.x & 31;
    const int row  = blockIdx.x * 8 + warp;
    if (row >= M) return;

    const float* s = S2 + (size_t)row * HID;
    float sv[HID / 32];  // 25 values per lane
    #pragma unroll
    for (int i = 0; i < HID / 32; ++i) sv[i] = s[lane + i * 32];

    float accv[NOUT];
    #pragma unroll
    for (int o = 0; o < NOUT; ++o) {
        float a = 0.0f;
        #pragma unroll
        for (int i = 0; i < HID / 32; ++i)
            a += sv[i] * w3s[o * HID + lane + i * 32];
        accv[o] = a;
    }
    #pragma unroll
    for (int o = 0; o < NOUT; ++o) {
        float v = accv[o];
        #pragma unroll
        for (int off = 16; off > 0; off >>= 1)
            v += __shfl_down_sync(0xffffffffu, v, off);
        if (lane == 0) C3[(size_t)row * NOUT + o] = v + b3[o];
    }
}

// ---------------------------------------------------------------------------
// LIF layer 3 + time-sum -> out[B,10]. One thread per (b, o).
// ---------------------------------------------------------------------------
__global__ void lif3_kernel(const float* __restrict__ C3,
                            float* __restrict__ s3r, float* __restrict__ out,
                            const float* __restrict__ beta_ptr)
{
    const int idx = blockIdx.x * blockDim.x + threadIdx.x;
    if (idx >= BATCH * NOUT) return;
    const float beta = fminf(fmaxf(beta_ptr[0], 0.0f), 1.0f);
    float mem = 0.0f, rst = 0.0f, sum = 0.0f;
    #pragma unroll
    for (int t = 0; t < T_STEPS; ++t) {
        const float c = C3[(size_t)t * BATCH * NOUT + idx];
        mem = beta * mem + c - rst;
        const float s = (mem - 1.0f > 0.0f) ? 1.0f : 0.0f;
        s3r[(size_t)t * BATCH * NOUT + idx] = s;
        sum += s;
        rst = s;
    }
    out[idx] = sum;
}

// ---------------------------------------------------------------------------
extern "C" void kernel_launch(void* const* d_in, const int* in_sizes, int n_in,
                              void* d_out, int out_size)
{
    const float* x     = (const float*)d_in[0];
    const float* W1    = (const float*)d_in[1];
    const float* b1    = (const float*)d_in[2];
    const float* W2    = (const float*)d_in[3];
    const float* b2    = (const float*)d_in[4];
    const float* W3    = (const float*)d_in[5];
    const float* b3    = (const float*)d_in[6];
    const float* beta1 = (const float*)d_in[7];
    const float* beta2 = (const float*)d_in[8];
    const float* beta3 = (const float*)d_in[9];

    float* out = (float*)d_out;
    float* s1r = out + (size_t)BATCH * NOUT;
    float* s2r = s1r + (size_t)M_ROWS * HID;
    float* s3r = s2r + (size_t)M_ROWS * HID;

    float *c1, *c2, *c3;
    cudaGetSymbolAddress((void**)&c1, g_c1);
    cudaGetSymbolAddress((void**)&c2, g_c2);
    cudaGetSymbolAddress((void**)&c3, g_c3);

    const int BH = BATCH * HID;  // 409600

    // 1) C1 = X @ W1^T + b1   [25600 x 800], K=784
    {
        dim3 grid((HID + 127) / 128, M_ROWS / 128);
        sgemm_nt_bias<<<grid, 256>>>(x, W1, b1, c1, M_ROWS, HID, DIN);
    }
    // 2) LIF layer 1 -> s1r
    lif_kernel<<<(BH + 255) / 256, 256>>>(c1, s1r, beta1, BH);

    // 3) C2 = S1 @ W2^T + b2   [25600 x 800], K=800
    {
        dim3 grid((HID + 127) / 128, M_ROWS / 128);
        sgemm_nt_bias<<<grid, 256>>>(s1r, W2, b2, c2, M_ROWS, HID, HID);
    }
    // 4) LIF layer 2 -> s2r
    lif_kernel<<<(BH + 255) / 256, 256>>>(c2, s2r, beta2, BH);

    // 5) C3 = S2 @ W3^T + b3   [25600 x 10]
    gemm3_kernel<<<M_ROWS / 8, 256>>>(s2r, W3, b3, c3, M_ROWS);

    // 6) LIF layer 3 + sum -> s3r, out
    lif3_kernel<<<(BATCH * NOUT + 255) / 256, 256>>>(c3, s3r, out, beta3);
}

// round 4
// speedup vs baseline: 1.1835x; 1.1835x over previous
#include <cuda_runtime.h>
#include <cstdint>

// ---------------------------------------------------------------------------
// ActivityDecaySNN: 3-layer LIF SNN forward. T=50, B=512, 784->800->800->10.
// BITWISE CONSTRAINT (discovered R1/R3): reference spikes have ~ulp-scale
// margins; outputs match ONLY if currents reproduce the ascending-k fp32 FMA
// chain of the reference GEMMs. So layers 1/2 use SIMT fp32 SGEMM (optimized),
// never tensor cores.
// d_out: out[512*10] | s1r[50*512*800] | s2r[50*512*800] | s3r[50*512*10]
// ---------------------------------------------------------------------------

#define T_STEPS 50
#define BATCH   512
#define DIN     784
#define HID     800
#define NOUT    10
#define M_ROWS  (T_STEPS * BATCH)   // 25600

__device__ float g_c1[(size_t)M_ROWS * HID];
__device__ float g_c2[(size_t)M_ROWS * HID];
__device__ float g_c3[(size_t)M_ROWS * NOUT];

// ===========================================================================
// SIMT SGEMM (NT): C[M,N] = A[M,K] @ W[N,K]^T + bias[N]
// BM=BN=128, templated BK (16 or 32), 256 threads, 8x8 microtile.
// Per-thread columns {tx*4..+3, 64+tx*4..+3}: conflict-free W-fragment LDS.
// Double-buffered smem; tile loads split into two half-groups to bound
// live registers. Ascending-k FMA chain per output element (bitwise-stable).
// ===========================================================================
template<int BK>
__global__ __launch_bounds__(256, 2)
void sgemm_nt(const float* __restrict__ A, const float* __restrict__ W,
              const float* __restrict__ bias, float* __restrict__ C,
              int M, int N, int K)
{
    constexpr int QPR    = BK / 4;        // float4 quads per tile row
    constexpr int ROWSPP = 256 / QPR;     // rows covered per load pass
    constexpr int NQ     = BK / 8;        // quads per thread per operand
    constexpr int HQ     = NQ / 2;        // quads per half-group (>=1)

    extern __shared__ float sm[];
    float* As = sm;                       // [2][BK][128]
    float* Ws = sm + 2 * BK * 128;        // [2][BK][128]

    const int tid = threadIdx.x;
    const int tx  = tid & 15;             // n-direction
    const int ty  = tid >> 4;             // m-direction
    const int m0  = blockIdx.y * 128;
    const int n0  = blockIdx.x * 128;

    const int ldCol = (tid % QPR) * 4;    // k offset within tile
    const int ldRow = tid / QPR;          // base row of this thread's quads

    float acc[8][8];
    #pragma unroll
    for (int i = 0; i < 8; ++i)
        #pragma unroll
        for (int j = 0; j < 8; ++j) acc[i][j] = 0.0f;

    const int numTiles = K / BK;
    const float4 z4 = make_float4(0.f, 0.f, 0.f, 0.f);

    // ---- prologue: stage tile 0 into buffer 0 ----
    #pragma unroll
    for (int p = 0; p < NQ; ++p) {
        const int r  = ldRow + p * ROWSPP;
        const float4 av = *reinterpret_cast<const float4*>(A + (size_t)(m0 + r) * K + ldCol);
        const int wn = n0 + r;
        const float4 wv = (wn < N)
            ? *reinterpret_cast<const float4*>(W + (size_t)wn * K + ldCol) : z4;
        #pragma unroll
        for (int q = 0; q < 4; ++q) {
            As[(ldCol + q) * 128 + r] = (&av.x)[q];
            Ws[(ldCol + q) * 128 + r] = (&wv.x)[q];
        }
    }
    __syncthreads();

    for (int t = 0; t < numTiles; ++t) {
        const int  buf     = t & 1;
        const int  nb      = buf ^ 1;
        const bool hasNext = (t + 1 < numTiles);
        const int  kn      = (t + 1) * BK;

        float* Ab = As + buf * BK * 128;
        float* Wb = Ws + buf * BK * 128;
        float* An = As + nb * BK * 128;
        float* Wn = Ws + nb * BK * 128;

        float4 pa[HQ], pw[HQ];

        // -- prefetch half 1 --
        if (hasNext) {
            #pragma unroll
            for (int p = 0; p < HQ; ++p) {
                const int r = ldRow + p * ROWSPP;
                pa[p] = *reinterpret_cast<const float4*>(A + (size_t)(m0 + r) * K + kn + ldCol);
                const int wn = n0 + r;
                pw[p] = (wn < N)
                    ? *reinterpret_cast<const float4*>(W + (size_t)wn * K + kn + ldCol) : z4;
            }
        }
        // -- compute first half of k --
        #pragma unroll
        for (int kk = 0; kk < BK / 2; ++kk) {
            float af[8], wf[8];
            *reinterpret_cast<float4*>(&af[0]) = *reinterpret_cast<const float4*>(Ab + kk * 128 + ty * 8);
            *reinterpret_cast<float4*>(&af[4]) = *reinterpret_cast<const float4*>(Ab + kk * 128 + ty * 8 + 4);
            *reinterpret_cast<float4*>(&wf[0]) = *reinterpret_cast<const float4*>(Wb + kk * 128 + tx * 4);
            *reinterpret_cast<float4*>(&wf[4]) = *reinterpret_cast<const float4*>(Wb + kk * 128 + 64 + tx * 4);
            #pragma unroll
            for (int i = 0; i < 8; ++i)
                #pragma unroll
                for (int j = 0; j < 8; ++j)
                    acc[i][j] += af[i] * wf[j];
        }
        // -- store half 1, prefetch half 2 --
        if (hasNext) {
            #pragma unroll
            for (int p = 0; p < HQ; ++p) {
                const int r = ldRow + p * ROWSPP;
                #pragma unroll
                for (int q = 0; q < 4; ++q) {
                    An[(ldCol + q) * 128 + r] = (&pa[p].x)[q];
                    Wn[(ldCol + q) * 128 + r] = (&pw[p].x)[q];
                }
            }
            #pragma unroll
            for (int p = 0; p < HQ; ++p) {
                const int r = ldRow + (HQ + p) * ROWSPP;
                pa[p] = *reinterpret_cast<const float4*>(A + (size_t)(m0 + r) * K + kn + ldCol);
                const int wn = n0 + r;
                pw[p] = (wn < N)
                    ? *reinterpret_cast<const float4*>(W + (size_t)wn * K + kn + ldCol) : z4;
            }
        }
        // -- compute second half of k --
        #pragma unroll
        for (int kk = BK / 2; kk < BK; ++kk) {
            float af[8], wf[8];
            *reinterpret_cast<float4*>(&af[0]) = *reinterpret_cast<const float4*>(Ab + kk * 128 + ty * 8);
            *reinterpret_cast<float4*>(&af[4]) = *reinterpret_cast<const float4*>(Ab + kk * 128 + ty * 8 + 4);
            *reinterpret_cast<float4*>(&wf[0]) = *reinterpret_cast<const float4*>(Wb + kk * 128 + tx * 4);
            *reinterpret_cast<float4*>(&wf[4]) = *reinterpret_cast<const float4*>(Wb + kk * 128 + 64 + tx * 4);
            #pragma unroll
            for (int i = 0; i < 8; ++i)
                #pragma unroll
                for (int j = 0; j < 8; ++j)
                    acc[i][j] += af[i] * wf[j];
        }
        // -- store half 2, publish buffer --
        if (hasNext) {
            #pragma unroll
            for (int p = 0; p < HQ; ++p) {
                const int r = ldRow + (HQ + p) * ROWSPP;
                #pragma unroll
                for (int q = 0; q < 4; ++q) {
                    An[(ldCol + q) * 128 + r] = (&pa[p].x)[q];
                    Wn[(ldCol + q) * 128 + r] = (&pw[p].x)[q];
                }
            }
            __syncthreads();
        }
    }

    // ---- epilogue: bias + store (float4 per column group; N % 4 == 0) ----
    #pragma unroll
    for (int i = 0; i < 8; ++i) {
        const int m = m0 + ty * 8 + i;
        {
            const int n = n0 + tx * 4;
            if (n < N) {
                float4 v;
                v.x = acc[i][0] + bias[n + 0];
                v.y = acc[i][1] + bias[n + 1];
                v.z = acc[i][2] + bias[n + 2];
                v.w = acc[i][3] + bias[n + 3];
                *reinterpret_cast<float4*>(C + (size_t)m * N + n) = v;
            }
        }
        {
            const int n = n0 + 64 + tx * 4;
            if (n < N) {
                float4 v;
                v.x = acc[i][4] + bias[n + 0];
                v.y = acc[i][5] + bias[n + 1];
                v.z = acc[i][6] + bias[n + 2];
                v.w = acc[i][7] + bias[n + 3];
                *reinterpret_cast<float4*>(C + (size_t)m * N + n) = v;
            }
        }
    }
}

// ===========================================================================
// LIF recurrence (bitwise-matching op order, proven in R1).
// ===========================================================================
__global__ void lif_kernel(const float* __restrict__ cur,
                           float* __restrict__ spk,
                           const float* __restrict__ beta_ptr, int BH)
{
    const int idx = blockIdx.x * blockDim.x + threadIdx.x;
    if (idx >= BH) return;
    const float beta = fminf(fmaxf(beta_ptr[0], 0.0f), 1.0f);
    float mem = 0.0f, rst = 0.0f;
    #pragma unroll
    for (int t = 0; t < T_STEPS; ++t) {
        const float c = cur[(size_t)t * BH + idx];
        mem = beta * mem + c - rst;
        const float s = (mem - 1.0f > 0.0f) ? 1.0f : 0.0f;
        spk[(size_t)t * BH + idx] = s;
        rst = s;
    }
}

__global__ __launch_bounds__(256)
void gemm3_kernel(const float* __restrict__ S2, const float* __restrict__ W3,
                  const float* __restrict__ b3, float* __restrict__ C3, int M)
{
    __shared__ float w3s[NOUT * HID];
    for (int i = threadIdx.x; i < NOUT * HID; i += 256) w3s[i] = W3[i];
    __syncthreads();

    const int warp = threadIdx.x >> 5;
    const int lane = threadIdx.x & 31;
    const int row  = blockIdx.x * 8 + warp;
    if (row >= M) return;

    const float* s = S2 + (size_t)row * HID;
    float sv[HID / 32];
    #pragma unroll
    for (int i = 0; i < HID / 32; ++i) sv[i] = s[lane + i * 32];

    float accv[NOUT];
    #pragma unroll
    for (int o = 0; o < NOUT; ++o) {
        float a = 0.0f;
        #pragma unroll
        for (int i = 0; i < HID / 32; ++i)
            a += sv[i] * w3s[o * HID + lane + i * 32];
        accv[o] = a;
    }
    #pragma unroll
    for (int o = 0; o < NOUT; ++o) {
        float v = accv[o];
        #pragma unroll
        for (int off = 16; off > 0; off >>= 1)
            v += __shfl_down_sync(0xffffffffu, v, off);
        if (lane == 0) C3[(size_t)row * NOUT + o] = v + b3[o];
    }
}

__global__ void lif3_kernel(const float* __restrict__ C3,
                            float* __restrict__ s3r, float* __restrict__ out,
                            const float* __restrict__ beta_ptr)
{
    const int idx = blockIdx.x * blockDim.x + threadIdx.x;
    if (idx >= BATCH * NOUT) return;
    const float beta = fminf(fmaxf(beta_ptr[0], 0.0f), 1.0f);
    float mem = 0.0f, rst = 0.0f, sum = 0.0f;
    #pragma unroll
    for (int t = 0; t < T_STEPS; ++t) {
        const float c = C3[(size_t)t * BATCH * NOUT + idx];
        mem = beta * mem + c - rst;
        const float s = (mem - 1.0f > 0.0f) ? 1.0f : 0.0f;
        s3r[(size_t)t * BATCH * NOUT + idx] = s;
        sum += s;
        rst = s;
    }
    out[idx] = sum;
}

// ===========================================================================
extern "C" void kernel_launch(void* const* d_in, const int* in_sizes, int n_in,
                              void* d_out, int out_size)
{
    const float* x     = (const float*)d_in[0];
    const float* W1    = (const float*)d_in[1];
    const float* b1    = (const float*)d_in[2];
    const float* W2    = (const float*)d_in[3];
    const float* b2    = (const float*)d_in[4];
    const float* W3    = (const float*)d_in[5];
    const float* b3    = (const float*)d_in[6];
    const float* beta1 = (const float*)d_in[7];
    const float* beta2 = (const float*)d_in[8];
    const float* beta3 = (const float*)d_in[9];

    float* out = (float*)d_out;
    float* s1r = out + (size_t)BATCH * NOUT;
    float* s2r = s1r + (size_t)M_ROWS * HID;
    float* s3r = s2r + (size_t)M_ROWS * HID;

    float *c1, *c2, *c3;
    cudaGetSymbolAddress((void**)&c1, g_c1);
    cudaGetSymbolAddress((void**)&c2, g_c2);
    cudaGetSymbolAddress((void**)&c3, g_c3);

    constexpr int SM16 = 4 * 16 * 128 * 4;   // 32 KB
    constexpr int SM32 = 4 * 32 * 128 * 4;   // 64 KB
    static bool attr_set = false;
    if (!attr_set) {
        cudaFuncSetAttribute(sgemm_nt<16>, cudaFuncAttributeMaxDynamicSharedMemorySize, SM16);
        cudaFuncSetAttribute(sgemm_nt<32>, cudaFuncAttributeMaxDynamicSharedMemorySize, SM32);
        attr_set = true;
    }

    const int BH = BATCH * HID;  // 409600
    const dim3 grid((HID + 127) / 128, M_ROWS / 128);

    // 1) C1 = X @ W1^T + b1   (K=784 -> BK=16, 49 tiles)
    sgemm_nt<16><<<grid, 256, SM16>>>(x, W1, b1, c1, M_ROWS, HID, DIN);

    // 2) LIF1 -> s1r
    lif_kernel<<<(BH + 255) / 256, 256>>>(c1, s1r, beta1, BH);

    // 3) C2 = S1 @ W2^T + b2  (K=800 -> BK=32, 25 tiles)
    sgemm_nt<32><<<grid, 256, SM32>>>(s1r, W2, b2, c2, M_ROWS, HID, HID);

    // 4) LIF2 -> s2r
    lif_kernel<<<(BH + 255) / 256, 256>>>(c2, s2r, beta2, BH);

    // 5) C3 = S2 @ W3^T + b3
    gemm3_kernel<<<M_ROWS / 8, 256>>>(s2r, W3, b3, c3, M_ROWS);

    // 6) LIF3 + sum
    lif3_kernel<<<(BATCH * NOUT + 255) / 256, 256>>>(c3, s3r, out, beta3);
}